// round 14
// baseline (speedup 1.0000x reference)
#include <cuda_runtime.h>

// QNN_72988674228630: 10-qubit, 2-layer RY+CNOT circuit, 8192 circuits.
//
// Bond-2 MPS transfer-matrix contraction, ONE thread per circuit (~250 ops).
//
// Derivation (bit p = 9 - qubit q; CNOT chain P = GF(2) suffix-XOR M):
//   psi = P R2 P R1 |0>,  out = sum_p <psi| Z_p |psi>
//   P^T Z_p P = Z_p Z_{p+1} ... Z_9             (suffix Z-string)
//   R2^T Z_m R2 = cos(t2) Z_m - sin(t2) X_m     (per site, FULL angle)
//   chi_j = prod_b f_b(j_b ^ j_{b+1})           (bond-2 MPS, f = (cos,sin) of t1/2)
// Contraction: symmetric 2x2 environment S swept p=9..0 with M = F_p S F_p
// (F_p = [[c,s],[s,c]]), then S <- (ga,-sg,-ga) . M.
//
// R14 simplifications found by auditing R12's algebra:
//  * The left diagonal environment obeys d' = (d0 c^2 + d1 s^2, d0 s^2 + d1 c^2)
//    from d=(1,1): since c^2+s^2=1, d == (1,1) IDENTICALLY (exact). So
//    E_{p+1} = trace(M) — the whole d-chain (18 regs, 16 FMA) was dead code.
//  * sincos(t2_p) is computed inside sweep iteration p (value needed only at
//    the end of the body): ga/sg live range 20 floats -> 2. Live set ~33
//    floats -> fully register-resident, zero spill pressure.
//  * E_0 = full contraction of the final S (off-diagonal twice).

__global__ __launch_bounds__(64, 1)
void qnn_kernel(const float* __restrict__ x,      // [128, 10]
                const float* __restrict__ w,      // [64, 10, 2]
                float* __restrict__ out)          // [64, 128] flat
{
    const int t  = blockIdx.x * 64 + threadIdx.x;   // 0..8191, one circuit
    const int of = t >> 7;          // out_feature (warp-uniform -> broadcast)
    const int nb = t & 127;         // batch row (coalesced across lanes)

    // --- Loads + angle prep. Bit p <-> qubit q = 9-p.
    //     t1h[p] = (x_q + w_q,layer0)/2 ; t2a[p] = w_q,layer1 (full angle).
    float t1h[10], t2a[10];
    {
        const float2* xp = (const float2*)(x + nb * 10);   // 8B-aligned (40B rows)
        const float4* wp = (const float4*)(w + of * 20);   // 16B-aligned (80B rows)
        float xv[10], wv[20];
#pragma unroll
        for (int i = 0; i < 5; i++) {
            const float2 v = xp[i];
            xv[2*i] = v.x; xv[2*i+1] = v.y;
        }
#pragma unroll
        for (int i = 0; i < 5; i++) {
            const float4 v = wp[i];
            wv[4*i] = v.x; wv[4*i+1] = v.y; wv[4*i+2] = v.z; wv[4*i+3] = v.w;
        }
#pragma unroll
        for (int q = 0; q < 10; q++) {
            t1h[9 - q] = 0.5f * (xv[q] + wv[2*q]);
            t2a[9 - q] = wv[2*q + 1];
        }
    }

    // --- MPS site factors f_p = (cos, sin) of the half layer-1 angle.
    float fc[10], fs[10];
#pragma unroll
    for (int p = 0; p < 10; p++)
        __sincosf(t1h[p], &fs[p], &fc[p]);

    // --- Top boundary (p = 9): S = (ga,-sg,-ga) . outer(f9, f9).
    float s00, s01, s11;
    {
        float gav, sgv; __sincosf(t2a[9], &sgv, &gav);
        const float c = fc[9], s = fs[9];
        s00 =  gav * (c * c);
        s01 = -sgv * (c * s);
        s11 = -gav * (s * s);
    }

    // --- Sweep p = 8..0: M = F_p S F_p; E_{p+1} = trace(M); S = g_p . M.
    float acc0 = 0.0f, acc1 = 0.0f;
#pragma unroll
    for (int p = 8; p >= 0; p--) {
        const float c = fc[p], s = fs[p];
        float gav, sgv; __sincosf(t2a[p], &sgv, &gav);   // hidden under FMA body
        const float t0  = fmaf(c, s00, s * s01);
        const float t1v = fmaf(c, s01, s * s11);
        const float t2v = fmaf(s, s00, c * s01);
        const float t3v = fmaf(s, s01, c * s11);
        const float M00 = fmaf(c, t0,  s * t1v);
        const float M01 = fmaf(s, t0,  c * t1v);
        const float M11 = fmaf(s, t2v, c * t3v);
        acc0 += M00;                 // E_{p+1} = M00 + M11 (left env == (1,1))
        acc1 += M11;
        s00 =  gav * M00;
        s01 = -sgv * M01;
        s11 = -gav * M11;
    }

    // --- E_0 = full contraction of S_0 (off-diagonal counted twice).
    out[t] = acc0 + acc1 + s00 + 2.0f * s01 + s11;
}

extern "C" void kernel_launch(void* const* d_in, const int* in_sizes, int n_in,
                              void* d_out, int out_size)
{
    const float* x = (const float*)d_in[0];   // (128, 10) fp32
    const float* w = (const float*)d_in[1];   // (64, 10, 2) fp32
    float* out = (float*)d_out;               // 8192 fp32

    // One thread per circuit: 128 blocks x 64 threads (best measured shape).
    qnn_kernel<<<128, 64>>>(x, w, out);
}